// round 12
// baseline (speedup 1.0000x reference)
#include <cuda_runtime.h>
#include <cuda_bf16.h>
#include <math.h>
#include <stdint.h>

#define NN 50000
#define NE 800000
#define HD 128
#define FNI 8
#define FEI 4
#define EGRID 296       // edge blocks = 148 SMs x occupancy 2 (fully resident)
#define NWT (NE/16)     // 50000 warp-tiles
#define NCHUNK 49       // ceil(NN/1024)

// ---------------- device scratch (no allocations allowed) ----------------
__device__ int   g_deg[NN];
__device__ int   g_off[NN+1];
__device__ int   g_cur[NN];
__device__ int   g_src[NE];
__device__ int   g_bsum[NCHUNK];
__device__ int   g_cnt;
__device__ float g_dinv[NN];
__device__ __nv_bfloat16 g_h1[NN*HD];   // h accumulator A (bf16)
__device__ __nv_bfloat16 g_h2[NN*HD];   // h accumulator B (bf16)
__device__ __nv_bfloat16 g_tb[NN*HD];   // bf16 message buffer
__device__ __nv_bfloat16 g_Ub[NN*HD];   // bf16 U = h@Wc1[0:128]
__device__ __nv_bfloat16 g_Vb[NN*HD];   // bf16 V = h@Wc1[128:256]
__device__ float g_c1p[HD];    // bc1 + be2 @ Wc1[256:384]
__device__ __nv_bfloat16 g_B1[HD*HD];   // M = We2@Wc1c, row-major [k][n], bf16
__device__ __nv_bfloat16 g_B2[HD*64];   // Wc2 row-major [k][n], bf16
__device__ __nv_bfloat16 g_B0[16*HD];   // [We1; be1; 0] augmented-K, [k][n], bf16
__device__ __nv_bfloat16 g_Wb2[HD*HD];  // bf16 W2
__device__ __nv_bfloat16 g_Wb3[HD*HD];  // bf16 W3
__device__ __nv_bfloat16 g_WbU[HD*HD];  // bf16 Wc1[0:128]
__device__ __nv_bfloat16 g_WbV[HD*HD];  // bf16 Wc1[128:256]

// ---------------- PTX helpers ----------------
__device__ __forceinline__ uint32_t smem_u32(const void* p) {
    uint32_t a;
    asm("{ .reg .u64 t; cvta.to.shared.u64 t, %1; cvt.u32.u64 %0, t; }" : "=r"(a) : "l"(p));
    return a;
}
__device__ __forceinline__ void ldsm_x4(uint32_t* r, uint32_t addr) {
    asm volatile("ldmatrix.sync.aligned.m8n8.x4.shared.b16 {%0,%1,%2,%3}, [%4];"
        : "=r"(r[0]), "=r"(r[1]), "=r"(r[2]), "=r"(r[3]) : "r"(addr));
}
__device__ __forceinline__ void ldsm_x4_t(uint32_t* r, uint32_t addr) {
    asm volatile("ldmatrix.sync.aligned.m8n8.x4.trans.shared.b16 {%0,%1,%2,%3}, [%4];"
        : "=r"(r[0]), "=r"(r[1]), "=r"(r[2]), "=r"(r[3]) : "r"(addr));
}
__device__ __forceinline__ void mma_bf16(float* d, const uint32_t* a, uint32_t b0, uint32_t b1) {
    asm volatile("mma.sync.aligned.m16n8k16.row.col.f32.bf16.bf16.f32 "
        "{%0,%1,%2,%3}, {%4,%5,%6,%7}, {%8,%9}, {%0,%1,%2,%3};"
        : "+f"(d[0]), "+f"(d[1]), "+f"(d[2]), "+f"(d[3])
        : "r"(a[0]), "r"(a[1]), "r"(a[2]), "r"(a[3]), "r"(b0), "r"(b1));
}
__device__ __forceinline__ uint32_t pack_bf16x2(float lo, float hi) {
    uint32_t p;
    asm("cvt.rn.bf16x2.f32 %0, %1, %2;" : "=r"(p) : "f"(hi), "f"(lo));
    return p;
}
__device__ __forceinline__ void acc_bf16x2(uint32_t u, float& lo, float& hi) {
    lo += __uint_as_float(u << 16);
    hi += __uint_as_float(u & 0xFFFF0000u);
}
__device__ __forceinline__ float bf_lo(uint32_t u) { return __uint_as_float(u << 16); }
__device__ __forceinline__ float bf_hi(uint32_t u) { return __uint_as_float(u & 0xFFFF0000u); }

// ---------------- degree / norm / CSR ----------------
__global__ void k_deg_count(const int* __restrict__ col) {
    int i = blockIdx.x*blockDim.x + threadIdx.x;
    if (i == 0) g_cnt = 0;   // reset scan rendezvous each replay
    if (i < NE) atomicAdd(&g_deg[col[i]], 1);
}
// single-pass scan: per-chunk scan -> publish chunk sum -> spin -> add base.
// 49 blocks, all resident; spin cannot deadlock.
__global__ __launch_bounds__(1024) void k_scan() {
    __shared__ int ws[32];
    __shared__ int sp[2];
    int tid = threadIdx.x, lane = tid & 31, w = tid >> 5;
    int chunk = blockIdx.x;
    int i = chunk*1024 + tid;
    int v = (i < NN) ? g_deg[i] : 0;
    if (i < NN) g_dinv[i] = rsqrtf((float)(v + 1));  // +1 self loop
    int x = v;
    #pragma unroll
    for (int d = 1; d < 32; d <<= 1) {
        int y = __shfl_up_sync(0xFFFFFFFFu, x, d);
        if (lane >= d) x += y;
    }
    if (lane == 31) ws[w] = x;
    __syncthreads();
    if (w == 0) {
        int y = ws[lane];
        #pragma unroll
        for (int d = 1; d < 32; d <<= 1) {
            int z = __shfl_up_sync(0xFFFFFFFFu, y, d);
            if (lane >= d) y += z;
        }
        ws[lane] = y;
    }
    __syncthreads();
    int excl = x - v + (w > 0 ? ws[w-1] : 0);
    int tot = ws[31];
    if (tid == 0) {
        g_bsum[chunk] = tot;
        __threadfence();
        atomicAdd(&g_cnt, 1);
        while (atomicAdd(&g_cnt, 0) < NCHUNK) { __nanosleep(64); }   // rendezvous
    }
    __syncthreads();
    if (tid < 64) {
        volatile int* bs = g_bsum;
        int bv = (tid < chunk) ? bs[tid] : 0;
        #pragma unroll
        for (int d = 16; d > 0; d >>= 1) bv += __shfl_down_sync(0xFFFFFFFFu, bv, d);
        if ((tid & 31) == 0) sp[tid >> 5] = bv;
    }
    __syncthreads();
    int base = sp[0] + sp[1];
    if (i < NN) {
        int o = excl + base;
        g_off[i] = o;
        g_cur[i] = o;
    }
    if (chunk == NCHUNK-1 && tid == 0) g_off[NN] = base + tot;
}
__global__ void k_fill(const int* __restrict__ row, const int* __restrict__ col) {
    int i = blockIdx.x*blockDim.x + threadIdx.x;
    if (i < NE) {
        int pos = atomicAdd(&g_cur[col[i]], 1);
        g_src[pos] = row[i];
    }
}

// ---------------- precompute: folded weights + bf16 weights ----------------
__global__ void k_prep(const float* __restrict__ We2, const float* __restrict__ Wc1,
                       const float* __restrict__ be2, const float* __restrict__ bc1,
                       const float* __restrict__ Wc2, const float* __restrict__ W2,
                       const float* __restrict__ W3, const float* __restrict__ We1,
                       const float* __restrict__ be1) {
    int idx = blockIdx.x*256 + threadIdx.x;   // 0..92159
    const float* Wc1c = Wc1 + 256*HD;
    if (idx < 16384) {
        int k = idx >> 7, n = idx & 127;
        float s = 0.f;
        for (int j = 0; j < HD; j++) s += __ldg(We2 + k*HD + j) * __ldg(Wc1c + j*HD + n);
        g_B1[idx] = __float2bfloat16(s);
        if (idx < 128) {
            float c = __ldg(bc1 + idx);
            for (int j = 0; j < HD; j++) c += __ldg(be2 + j) * __ldg(Wc1c + j*HD + idx);
            g_c1p[idx] = c;
        }
    } else if (idx < 24576) {
        int t = idx - 16384;
        g_B2[t] = __float2bfloat16(__ldg(Wc2 + t));
    } else if (idx < 40960) {
        int t = idx - 24576;
        g_Wb2[t] = __float2bfloat16(__ldg(W2 + t));
    } else if (idx < 57344) {
        int t = idx - 40960;
        g_Wb3[t] = __float2bfloat16(__ldg(W3 + t));
    } else if (idx < 73728) {
        int t = idx - 57344;
        g_WbU[t] = __float2bfloat16(__ldg(Wc1 + t));
    } else if (idx < 90112) {
        int t = idx - 73728;
        g_WbV[t] = __float2bfloat16(__ldg(Wc1 + HD*HD + t));
    } else if (idx < 92160) {
        int e = idx - 90112;      // 16x128 augmented [We1; be1; 0]
        int k = e >> 7, n = e & 127;
        float v = (k < 4) ? __ldg(We1 + k*HD + n) : (k == 4 ? __ldg(be1 + n) : 0.f);
        g_B0[e] = __float2bfloat16(v);
    }
}

// ---------------- layer-1 transform (K=8): tb = bf16(dinv * (x@W1)) ----------------
__global__ void k_transform1(const float* __restrict__ x, const float* __restrict__ W1,
                             __nv_bfloat16* __restrict__ tout) {
    __shared__ float sx[64*FNI];
    __shared__ float sw[FNI*HD];
    int tid = threadIdx.x;  // 0..127
    for (int i = tid; i < FNI*HD; i += 128) sw[i] = W1[i];
    int r0 = blockIdx.x * 64;
    for (int i = tid; i < 64*FNI; i += 128) {
        int r = r0 + (i >> 3);
        sx[i] = (r < NN) ? x[r*FNI + (i & 7)] : 0.f;
    }
    __syncthreads();
    int c = (tid & 63) * 2;
    int half = tid >> 6;
    for (int m = half*32; m < half*32 + 32; m++) {
        int r = r0 + m;
        if (r >= NN) break;
        float a0 = 0.f, a1 = 0.f;
        #pragma unroll
        for (int k = 0; k < FNI; k++) {
            float xv = sx[m*FNI + k];
            a0 += xv * sw[k*HD + c];
            a1 += xv * sw[k*HD + c + 1];
        }
        float d = g_dinv[r];
        ((uint32_t*)tout)[(size_t)r*64 + (c >> 1)] = pack_bf16x2(d*a0, d*a1);
    }
}

// ---------------- node GEMM via mma.sync bf16 (bf16 A): outb = bf16(dinv*(A@Wb)) ----------------
#define NSTR 136
#define O_NW 34816
#define SMEM_NODE_BYTES 69632

__global__ __launch_bounds__(256, 2) void k_node_mma(const __nv_bfloat16* __restrict__ A,
        const __nv_bfloat16* __restrict__ Wb,
        __nv_bfloat16* __restrict__ outb) {
    extern __shared__ char smem[];
    uint32_t sbase = smem_u32(smem);
    uint32_t* sAu = (uint32_t*)smem;
    uint32_t* sWu = (uint32_t*)(smem + O_NW);
    int tid = threadIdx.x, wid = tid >> 5, lane = tid & 31;
    int r0 = blockIdx.x * 128;

    const uint32_t* wsrc = (const uint32_t*)Wb;
    const uint32_t* asrc = (const uint32_t*)A;
    for (int i = tid; i < 8192; i += 256) {
        int r = i >> 6, cp = i & 63;
        sWu[r*(NSTR/2) + cp] = __ldg(wsrc + i);
    }
    for (int i = tid; i < 8192; i += 256) {
        int m = i >> 6, kp = i & 63;
        int r = r0 + m; if (r >= NN) r = NN - 1;
        sAu[m*(NSTR/2) + kp] = __ldg(asrc + (size_t)r*64 + kp);
    }
    __syncthreads();

    int lr = lane & 15, lc = (lane >> 4) << 3;
    float acc[16][4];
    #pragma unroll
    for (int i = 0; i < 16; i++)
        #pragma unroll
        for (int j = 0; j < 4; j++) acc[i][j] = 0.f;
    #pragma unroll
    for (int k0 = 0; k0 < 8; k0++) {
        uint32_t a[4];
        ldsm_x4(a, sbase + ((16*wid + lr)*NSTR + k0*16 + lc)*2);
        #pragma unroll
        for (int nt2 = 0; nt2 < 8; nt2++) {
            uint32_t b[4];
            ldsm_x4_t(b, sbase + O_NW + ((k0*16 + lr)*NSTR + nt2*16 + lc)*2);
            mma_bf16(acc[2*nt2],     a, b[0], b[1]);
            mma_bf16(acc[2*nt2 + 1], a, b[2], b[3]);
        }
    }

    int rA = r0 + 16*wid + (lane >> 2);
    int rB = rA + 8;
    int q = lane & 3;
    if (rA < NN) {
        float s = g_dinv[rA];
        uint32_t* ob = (uint32_t*)outb + (size_t)rA*64;
        #pragma unroll
        for (int nt = 0; nt < 16; nt++)
            ob[nt*4 + q] = pack_bf16x2(acc[nt][0]*s, acc[nt][1]*s);
    }
    if (rB < NN) {
        float s = g_dinv[rB];
        uint32_t* ob = (uint32_t*)outb + (size_t)rB*64;
        #pragma unroll
        for (int nt = 0; nt < 16; nt++)
            ob[nt*4 + q] = pack_bf16x2(acc[nt][2]*s, acc[nt][3]*s);
    }
}

// ---------------- fused U/V GEMM: ub = bf16(A@WbU), vb = bf16(A@WbV) ----------------
#define O_UVW1 34816
#define O_UVW2 69632
#define SMEM_UV_BYTES 104448

__global__ __launch_bounds__(256, 2) void k_node_uv(const __nv_bfloat16* __restrict__ A,
        const __nv_bfloat16* __restrict__ WU, const __nv_bfloat16* __restrict__ WV,
        __nv_bfloat16* __restrict__ ub, __nv_bfloat16* __restrict__ vb) {
    extern __shared__ char smem[];
    uint32_t sbase = smem_u32(smem);
    uint32_t* sAu = (uint32_t*)smem;
    uint32_t* sW1 = (uint32_t*)(smem + O_UVW1);
    uint32_t* sW2 = (uint32_t*)(smem + O_UVW2);
    int tid = threadIdx.x, wid = tid >> 5, lane = tid & 31;
    int r0 = blockIdx.x * 128;

    const uint32_t* w1 = (const uint32_t*)WU;
    const uint32_t* w2 = (const uint32_t*)WV;
    const uint32_t* asrc = (const uint32_t*)A;
    for (int i = tid; i < 8192; i += 256) {
        int r = i >> 6, cp = i & 63;
        sW1[r*(NSTR/2) + cp] = __ldg(w1 + i);
        sW2[r*(NSTR/2) + cp] = __ldg(w2 + i);
    }
    for (int i = tid; i < 8192; i += 256) {
        int m = i >> 6, kp = i & 63;
        int r = r0 + m; if (r >= NN) r = NN - 1;
        sAu[m*(NSTR/2) + kp] = __ldg(asrc + (size_t)r*64 + kp);
    }
    __syncthreads();

    int lr = lane & 15, lc = (lane >> 4) << 3;
    int rA = r0 + 16*wid + (lane >> 2);
    int rB = rA + 8;
    int q = lane & 3;

    #pragma unroll
    for (int pass = 0; pass < 2; pass++) {
        uint32_t wbase = pass ? (sbase + O_UVW2) : (sbase + O_UVW1);
        float acc[16][4];
        #pragma unroll
        for (int i = 0; i < 16; i++)
            #pragma unroll
            for (int j = 0; j < 4; j++) acc[i][j] = 0.f;
        #pragma unroll
        for (int k0 = 0; k0 < 8; k0++) {
            uint32_t a[4];
            ldsm_x4(a, sbase + ((16*wid + lr)*NSTR + k0*16 + lc)*2);
            #pragma unroll
            for (int nt2 = 0; nt2 < 8; nt2++) {
                uint32_t b[4];
                ldsm_x4_t(b, wbase + ((k0*16 + lr)*NSTR + nt2*16 + lc)*2);
                mma_bf16(acc[2*nt2],     a, b[0], b[1]);
                mma_bf16(acc[2*nt2 + 1], a, b[2], b[3]);
            }
        }
        __nv_bfloat16* outp = pass ? vb : ub;
        if (rA < NN) {
            uint32_t* ob = (uint32_t*)outp + (size_t)rA*64;
            #pragma unroll
            for (int nt = 0; nt < 16; nt++)
                ob[nt*4 + q] = pack_bf16x2(acc[nt][0], acc[nt][1]);
        }
        if (rB < NN) {
            uint32_t* ob = (uint32_t*)outp + (size_t)rB*64;
            #pragma unroll
            for (int nt = 0; nt < 16; nt++)
                ob[nt*4 + q] = pack_bf16x2(acc[nt][2], acc[nt][3]);
        }
    }
}

// ---------------- CSR gather-aggregate (bf16 in/out, unroll-8) ----------------
__global__ __launch_bounds__(256) void k_aggregate(const __nv_bfloat16* __restrict__ t,
        const float* __restrict__ b, __nv_bfloat16* __restrict__ outp) {
    int wid = threadIdx.x >> 5, lane = threadIdx.x & 31;
    int c = blockIdx.x * 8 + wid;
    int start = __ldg(&g_off[c]), end = __ldg(&g_off[c+1]);
    const uint2* T = (const uint2*)t;   // 32 uint2 per row (128 bf16)
    float ax = 0.f, ay = 0.f, az = 0.f, aw = 0.f;
    {   // self term
        uint2 sv = __ldg(T + (size_t)c*32 + lane);
        acc_bf16x2(sv.x, ax, ay);
        acc_bf16x2(sv.y, az, aw);
    }
    for (int base = start; base < end; base += 32) {
        int n = end - base;
        int myIdx = (lane < n) ? __ldg(&g_src[base + lane]) : 0;
        int cnt = min(32, n);
        int j = 0;
        for (; j + 8 <= cnt; j += 8) {
            uint2 v[8];
            #pragma unroll
            for (int u = 0; u < 8; u++) {
                int r = __shfl_sync(0xFFFFFFFFu, myIdx, j + u);
                v[u] = __ldg(T + (size_t)r*32 + lane);
            }
            #pragma unroll
            for (int u = 0; u < 8; u++) {
                acc_bf16x2(v[u].x, ax, ay);
                acc_bf16x2(v[u].y, az, aw);
            }
        }
        for (; j + 4 <= cnt; j += 4) {
            uint2 v[4];
            #pragma unroll
            for (int u = 0; u < 4; u++) {
                int r = __shfl_sync(0xFFFFFFFFu, myIdx, j + u);
                v[u] = __ldg(T + (size_t)r*32 + lane);
            }
            #pragma unroll
            for (int u = 0; u < 4; u++) {
                acc_bf16x2(v[u].x, ax, ay);
                acc_bf16x2(v[u].y, az, aw);
            }
        }
        for (; j < cnt; j++) {
            int r = __shfl_sync(0xFFFFFFFFu, myIdx, j);
            uint2 v = __ldg(T + (size_t)r*32 + lane);
            acc_bf16x2(v.x, ax, ay);
            acc_bf16x2(v.y, az, aw);
        }
    }
    float d = g_dinv[c];
    float4 bb = __ldg((const float4*)b + lane);
    uint2 o;
    o.x = pack_bf16x2(fmaxf(d*ax + bb.x, 0.f), fmaxf(d*ay + bb.y, 0.f));
    o.y = pack_bf16x2(fmaxf(d*az + bb.z, 0.f), fmaxf(d*aw + bb.w, 0.f));
    ((uint2*)outp)[(size_t)c*32 + lane] = o;
}

// ---------------- fused edge MLP: sync-free, register-chained mma ----------------
#define SAS 136
#define SBS 72
#define O_SB1   0          // 128 x 68 words
#define O_SB2   34816      // 128 x 36 words
#define O_SW0   53248      // 16 x 68 words (B0 augmented)
#define O_SC1P  57600      // 128 f32
#define O_SWC3  58112      // 128 f32
#define O_SBC2  58624      // 64 f32
#define SMEM_EDGE_BYTES 58880

__global__ __launch_bounds__(256, 2) void k_edge_mlp(
        const int* __restrict__ row, const int* __restrict__ col,
        const float* __restrict__ ea,
        const float* __restrict__ bc2, const float* __restrict__ Wc3,
        const float* __restrict__ bc3,
        const uint32_t* __restrict__ U, const uint32_t* __restrict__ V,
        float* __restrict__ out) {
    extern __shared__ char smem[];
    uint32_t sbase = smem_u32(smem);
    int tid = threadIdx.x;
    int wid = tid >> 5, lane = tid & 31;

    float* sC1p = (float*)(smem + O_SC1P);
    float* sWc3 = (float*)(smem + O_SWC3);
    float* sbc2 = (float*)(smem + O_SBC2);
    uint32_t* sB1u = (uint32_t*)(smem + O_SB1);
    uint32_t* sB2u = (uint32_t*)(smem + O_SB2);
    uint32_t* sW0u = (uint32_t*)(smem + O_SW0);

    // ---- persistent loads (once per block) ----
    if (tid < 128) {
        sC1p[tid] = g_c1p[tid];
        sWc3[tid] = __ldg(Wc3 + tid);
        if (tid < 64) sbc2[tid] = __ldg(bc2 + tid);
    }
    {
        const uint32_t* src = (const uint32_t*)g_B1;
        for (int i = tid; i < 8192; i += 256) {
            int r = i >> 6, cp = i & 63;
            sB1u[r*(SAS/2) + cp] = __ldg(src + i);
        }
    }
    {
        const uint32_t* src = (const uint32_t*)g_B2;
        for (int i = tid; i < 4096; i += 256) {
            int r = i >> 5, cp = i & 31;
            sB2u[r*(SBS/2) + cp] = __ldg(src + i);
        }
    }
    {
        const uint32_t* src = (const uint32_t*)g_B0;
        for (int i = tid; i < 1024; i += 256) {
            int r = i >> 6, cp = i & 63;
            sW0u[r*(SAS/2) + cp] = __ldg(src + i);
        }
    }
    __syncthreads();   // the only block-wide sync

    int lr = lane & 15, lc = (lane >> 4) << 3;
    int g = lane >> 2, t = lane & 3;
    float c3a = __ldg(bc3 + 0), c3b = __ldg(bc3 + 1);

    for (int wt = blockIdx.x*8 + wid; wt < NWT; wt += EGRID*8) {
        int e0 = wt * 16;
        int eA = e0 + g, eB = eA + 8;
        int rI0 = __ldg(row + eA), cI0 = __ldg(col + eA);
        int rI1 = __ldg(row + eB), cI1 = __ldg(col + eB);

        // ea A-fragments with augmented K (k=4 is the ones column -> bias)
        uint32_t eaf[4];
        eaf[2] = 0; eaf[3] = 0;
        if (t < 2) {
            float2 vA = *(const float2*)(ea + (size_t)eA*4 + 2*t);
            float2 vB = *(const float2*)(ea + (size_t)eB*4 + 2*t);
            eaf[0] = pack_bf16x2(vA.x, vA.y);
            eaf[1] = pack_bf16x2(vB.x, vB.y);
        } else if (t == 2) {
            eaf[0] = 0x00003F80u;   // (1.0, 0.0) bf16x2
            eaf[1] = 0x00003F80u;
        } else {
            eaf[0] = 0; eaf[1] = 0;
        }

        float acc[16][4];
        #pragma unroll
        for (int i = 0; i < 16; i++)
            #pragma unroll
            for (int j = 0; j < 4; j++) acc[i][j] = 0.f;

        // mma0: acc = [ea,1] @ [We1;be1]  (K=16, single k-step)
        #pragma unroll
        for (int nt2 = 0; nt2 < 8; nt2++) {
            uint32_t b[4];
            ldsm_x4_t(b, sbase + O_SW0 + (lr*SAS + nt2*16 + lc)*2);
            mma_bf16(acc[2*nt2],     eaf, b[0], b[1]);
            mma_bf16(acc[2*nt2 + 1], eaf, b[2], b[3]);
        }

        // relu -> A-fragments for GEMM1 (D->A register conversion)
        uint32_t af[8][4];
        #pragma unroll
        for (int kt = 0; kt < 8; kt++) {
            af[kt][0] = pack_bf16x2(fmaxf(acc[2*kt][0],   0.f), fmaxf(acc[2*kt][1],   0.f));
            af[kt][1] = pack_bf16x2(fmaxf(acc[2*kt][2],   0.f), fmaxf(acc[2*kt][3],   0.f));
            af[kt][2] = pack_bf16x2(fmaxf(acc[2*kt+1][0], 0.f), fmaxf(acc[2*kt+1][1], 0.f));
            af[kt][3] = pack_bf16x2(fmaxf(acc[2*kt+1][2], 0.f), fmaxf(acc[2*kt+1][3], 0.f));
        }

        // GEMM1: acc = a @ M
        #pragma unroll
        for (int i = 0; i < 16; i++)
            #pragma unroll
            for (int j = 0; j < 4; j++) acc[i][j] = 0.f;
        #pragma unroll
        for (int k0 = 0; k0 < 8; k0++) {
            #pragma unroll
            for (int nt2 = 0; nt2 < 8; nt2++) {
                uint32_t b[4];
                ldsm_x4_t(b, sbase + O_SB1 + ((k0*16 + lr)*SAS + nt2*16 + lc)*2);
                mma_bf16(acc[2*nt2],     af[k0], b[0], b[1]);
                mma_bf16(acc[2*nt2 + 1], af[k0], b[2], b[3]);
            }
        }

        // epilogue1: z1 = relu(acc + U[row] + V[col] + c1p) -> A-frags (in regs)
        {
            const uint32_t* U0 = U + (size_t)rI0*64;
            const uint32_t* V0 = V + (size_t)cI0*64;
            const uint32_t* U1 = U + (size_t)rI1*64;
            const uint32_t* V1 = V + (size_t)cI1*64;
            #pragma unroll
            for (int kt = 0; kt < 8; kt++) {
                int cw0 = kt*8 + t;
                int cw1 = kt*8 + 4 + t;
                uint32_t uA0 = __ldg(U0 + cw0), vA0 = __ldg(V0 + cw0);
                uint32_t uB0 = __ldg(U1 + cw0), vB0 = __ldg(V1 + cw0);
                uint32_t uA1 = __ldg(U0 + cw1), vA1 = __ldg(V0 + cw1);
                uint32_t uB1 = __ldg(U1 + cw1), vB1 = __ldg(V1 + cw1);
                int c0 = cw0*2, c1 = cw1*2;
                float p00 = sC1p[c0], p01 = sC1p[c0+1];
                float p10 = sC1p[c1], p11 = sC1p[c1+1];
                af[kt][0] = pack_bf16x2(
                    fmaxf(acc[2*kt][0] + bf_lo(uA0) + bf_lo(vA0) + p00, 0.f),
                    fmaxf(acc[2*kt][1] + bf_hi(uA0) + bf_hi(vA0) + p01, 0.f));
                af[kt][1] = pack_bf16x2(
                    fmaxf(acc[2*kt][2] + bf_lo(uB0) + bf_lo(vB0) + p00, 0.f),
                    fmaxf(acc[2*kt][3] + bf_hi(uB0) + bf_hi(vB0) + p01, 0.f));
                af[kt][2] = pack_bf16x2(
                    fmaxf(acc[2*kt+1][0] + bf_lo(uA1) + bf_lo(vA1) + p10, 0.f),
                    fmaxf(acc[2*kt+1][1] + bf_hi(uA1) + bf_hi(vA1) + p11, 0.f));
                af[kt][3] = pack_bf16x2(
                    fmaxf(acc[2*kt+1][2] + bf_lo(uB1) + bf_lo(vB1) + p10, 0.f),
                    fmaxf(acc[2*kt+1][3] + bf_hi(uB1) + bf_hi(vB1) + p11, 0.f));
            }
        }

        // GEMM2: acc[0..7] = z1 @ Wc2
        #pragma unroll
        for (int i = 0; i < 8; i++)
            #pragma unroll
            for (int j = 0; j < 4; j++) acc[i][j] = 0.f;
        #pragma unroll
        for (int k0 = 0; k0 < 8; k0++) {
            #pragma unroll
            for (int nt2 = 0; nt2 < 4; nt2++) {
                uint32_t b[4];
                ldsm_x4_t(b, sbase + O_SB2 + ((k0*16 + lr)*SBS + nt2*16 + lc)*2);
                mma_bf16(acc[2*nt2],     af[k0], b[0], b[1]);
                mma_bf16(acc[2*nt2 + 1], af[k0], b[2], b[3]);
            }
        }

        // epilogue2: z2 = relu(acc + bc2); logits; log_softmax
        {
            float l0a = 0.f, l1a = 0.f, l0b = 0.f, l1b = 0.f;
            #pragma unroll
            for (int nt = 0; nt < 8; nt++) {
                int c = nt*8 + 2*t;
                float b0 = sbc2[c], b1 = sbc2[c+1];
                float w00 = sWc3[2*c],   w01 = sWc3[2*c+1];
                float w10 = sWc3[2*c+2], w11 = sWc3[2*c+3];
                float za = fmaxf(acc[nt][0] + b0, 0.f);
                float zb = fmaxf(acc[nt][1] + b1, 0.f);
                l0a += za*w00 + zb*w10;
                l1a += za*w01 + zb*w11;
                float zc = fmaxf(acc[nt][2] + b0, 0.f);
                float zd = fmaxf(acc[nt][3] + b1, 0.f);
                l0b += zc*w00 + zd*w10;
                l1b += zc*w01 + zd*w11;
            }
            #pragma unroll
            for (int off = 1; off <= 2; off <<= 1) {
                l0a += __shfl_xor_sync(0xFFFFFFFFu, l0a, off);
                l1a += __shfl_xor_sync(0xFFFFFFFFu, l1a, off);
                l0b += __shfl_xor_sync(0xFFFFFFFFu, l0b, off);
                l1b += __shfl_xor_sync(0xFFFFFFFFu, l1b, off);
            }
            if (t == 0) {
                float L0 = l0a + c3a, L1 = l1a + c3b;
                float mx = fmaxf(L0, L1);
                float lse = mx + logf(expf(L0 - mx) + expf(L1 - mx));
                size_t o = (size_t)eA * 2;
                out[o + 0] = L0 - lse;
                out[o + 1] = L1 - lse;
                L0 = l0b + c3a; L1 = l1b + c3b;
                mx = fmaxf(L0, L1);
                lse = mx + logf(expf(L0 - mx) + expf(L1 - mx));
                o = (size_t)eB * 2;
                out[o + 0] = L0 - lse;
                out[o + 1] = L1 - lse;
            }
        }
    }
}

// ---------------- launch ----------------
extern "C" void kernel_launch(void* const* d_in, const int* in_sizes, int n_in,
                              void* d_out, int out_size) {
    const float* x   = (const float*)d_in[0];
    const int*   ei  = (const int*)  d_in[1];
    const float* ea  = (const float*)d_in[2];
    const float* W1  = (const float*)d_in[3];
    const float* b1  = (const float*)d_in[4];
    const float* W2  = (const float*)d_in[5];
    const float* b2  = (const float*)d_in[6];
    const float* W3  = (const float*)d_in[7];
    const float* b3  = (const float*)d_in[8];
    const float* We1 = (const float*)d_in[9];
    const float* be1 = (const float*)d_in[10];
    const float* We2 = (const float*)d_in[11];
    const float* be2 = (const float*)d_in[12];
    const float* Wc1 = (const float*)d_in[13];
    const float* bc1 = (const float*)d_in[14];
    const float* Wc2 = (const float*)d_in[15];
    const float* bc2 = (const float*)d_in[16];
    const float* Wc3 = (const float*)d_in[17];
    const float* bc3 = (const float*)d_in[18];
    float* out = (float*)d_out;
    const int* row = ei;
    const int* col = ei + NE;

    __nv_bfloat16 *h1, *h2, *tb, *ub, *vb;
    cudaGetSymbolAddress((void**)&h1, g_h1);
    cudaGetSymbolAddress((void**)&h2, g_h2);
    cudaGetSymbolAddress((void**)&tb, g_tb);
    cudaGetSymbolAddress((void**)&ub, g_Ub);
    cudaGetSymbolAddress((void**)&vb, g_Vb);
    __nv_bfloat16 *wb2, *wb3, *wbu, *wbv;
    cudaGetSymbolAddress((void**)&wb2, g_Wb2);
    cudaGetSymbolAddress((void**)&wb3, g_Wb3);
    cudaGetSymbolAddress((void**)&wbu, g_WbU);
    cudaGetSymbolAddress((void**)&wbv, g_WbV);
    int* degp;
    cudaGetSymbolAddress((void**)&degp, g_deg);

    cudaFuncSetAttribute(k_node_mma, cudaFuncAttributeMaxDynamicSharedMemorySize, SMEM_NODE_BYTES);
    cudaFuncSetAttribute(k_node_uv,  cudaFuncAttributeMaxDynamicSharedMemorySize, SMEM_UV_BYTES);
    cudaFuncSetAttribute(k_edge_mlp, cudaFuncAttributeMaxDynamicSharedMemorySize, SMEM_EDGE_BYTES);

    // graph preprocessing
    cudaMemsetAsync(degp, 0, NN*sizeof(int));
    k_deg_count<<<(NE + 255)/256, 256>>>(col);
    k_scan     <<<NCHUNK, 1024>>>();
    k_fill     <<<(NE + 255)/256, 256>>>(row, col);
    k_prep     <<<360, 256>>>(We2, Wc1, be2, bc1, Wc2, W2, W3, We1, be1);

    const int NB = (NN + 127)/128;
    // layer 1
    k_transform1<<<(NN + 63)/64, 128>>>(x, W1, tb);
    k_aggregate <<<NN/8, 256>>>(tb, b1, h1);
    // layer 2
    k_node_mma  <<<NB, 256, SMEM_NODE_BYTES>>>(h1, wb2, tb);
    k_aggregate <<<NN/8, 256>>>(tb, b2, h2);
    // layer 3
    k_node_mma  <<<NB, 256, SMEM_NODE_BYTES>>>(h2, wb3, tb);
    k_aggregate <<<NN/8, 256>>>(tb, b3, h1);

    // U = h@Wc1[0:128], V = h@Wc1[128:256]  (fused, bf16)
    k_node_uv   <<<NB, 256, SMEM_UV_BYTES>>>(h1, wbu, wbv, ub, vb);

    k_edge_mlp<<<EGRID, 256, SMEM_EDGE_BYTES>>>(row, col, ea,
                                                bc2, Wc3, bc3,
                                                (const uint32_t*)ub, (const uint32_t*)vb, out);
}

// round 13
// speedup vs baseline: 1.0115x; 1.0115x over previous
#include <cuda_runtime.h>
#include <cuda_bf16.h>
#include <math.h>
#include <stdint.h>

#define NN 50000
#define NE 800000
#define HD 128
#define FNI 8
#define FEI 4
#define EGRID 296       // edge blocks = 148 SMs x occupancy 2 (fully resident)
#define NWT (NE/16)     // 50000 warp-tiles
#define NCHUNK 49       // ceil(NN/1024)

// ---------------- device scratch (no allocations allowed) ----------------
__device__ int   g_deg[NN];
__device__ int   g_off[NN+1];
__device__ int   g_cur[NN];
__device__ int   g_src[NE];
__device__ int   g_bsum[NCHUNK];
__device__ float g_dinv[NN];
__device__ __nv_bfloat16 g_h1[NN*HD];   // h accumulator A (bf16)
__device__ __nv_bfloat16 g_h2[NN*HD];   // h accumulator B (bf16)
__device__ __nv_bfloat16 g_tb[NN*HD];   // bf16 message buffer
__device__ __nv_bfloat16 g_Ub[NN*HD];   // bf16 U = h@Wc1[0:128]
__device__ __nv_bfloat16 g_Vb[NN*HD];   // bf16 V = h@Wc1[128:256]
__device__ float g_c1p[HD];    // bc1 + be2 @ Wc1[256:384]
__device__ __nv_bfloat16 g_B1[HD*HD];   // M = We2@Wc1c, row-major [k][n], bf16
__device__ __nv_bfloat16 g_B2[HD*64];   // Wc2 row-major [k][n], bf16
__device__ __nv_bfloat16 g_B0[16*HD];   // [We1; be1; 0] augmented-K, [k][n], bf16
__device__ __nv_bfloat16 g_Wb2[HD*HD];  // bf16 W2
__device__ __nv_bfloat16 g_Wb3[HD*HD];  // bf16 W3
__device__ __nv_bfloat16 g_WbU[HD*HD];  // bf16 Wc1[0:128]
__device__ __nv_bfloat16 g_WbV[HD*HD];  // bf16 Wc1[128:256]

// ---------------- PTX helpers ----------------
__device__ __forceinline__ uint32_t smem_u32(const void* p) {
    uint32_t a;
    asm("{ .reg .u64 t; cvta.to.shared.u64 t, %1; cvt.u32.u64 %0, t; }" : "=r"(a) : "l"(p));
    return a;
}
__device__ __forceinline__ void ldsm_x4(uint32_t* r, uint32_t addr) {
    asm volatile("ldmatrix.sync.aligned.m8n8.x4.shared.b16 {%0,%1,%2,%3}, [%4];"
        : "=r"(r[0]), "=r"(r[1]), "=r"(r[2]), "=r"(r[3]) : "r"(addr));
}
__device__ __forceinline__ void ldsm_x4_t(uint32_t* r, uint32_t addr) {
    asm volatile("ldmatrix.sync.aligned.m8n8.x4.trans.shared.b16 {%0,%1,%2,%3}, [%4];"
        : "=r"(r[0]), "=r"(r[1]), "=r"(r[2]), "=r"(r[3]) : "r"(addr));
}
__device__ __forceinline__ void mma_bf16(float* d, const uint32_t* a, uint32_t b0, uint32_t b1) {
    asm volatile("mma.sync.aligned.m16n8k16.row.col.f32.bf16.bf16.f32 "
        "{%0,%1,%2,%3}, {%4,%5,%6,%7}, {%8,%9}, {%0,%1,%2,%3};"
        : "+f"(d[0]), "+f"(d[1]), "+f"(d[2]), "+f"(d[3])
        : "r"(a[0]), "r"(a[1]), "r"(a[2]), "r"(a[3]), "r"(b0), "r"(b1));
}
__device__ __forceinline__ uint32_t pack_bf16x2(float lo, float hi) {
    uint32_t p;
    asm("cvt.rn.bf16x2.f32 %0, %1, %2;" : "=r"(p) : "f"(hi), "f"(lo));
    return p;
}
__device__ __forceinline__ void acc_bf16x2(uint32_t u, float& lo, float& hi) {
    lo += __uint_as_float(u << 16);
    hi += __uint_as_float(u & 0xFFFF0000u);
}
__device__ __forceinline__ float bf_lo(uint32_t u) { return __uint_as_float(u << 16); }
__device__ __forceinline__ float bf_hi(uint32_t u) { return __uint_as_float(u & 0xFFFF0000u); }

// ---------------- degree / norm / CSR ----------------
__global__ void k_deg_count(const int* __restrict__ col) {
    int i = blockIdx.x*blockDim.x + threadIdx.x;
    if (i < NE) atomicAdd(&g_deg[col[i]], 1);
}
__global__ __launch_bounds__(1024) void k_scanA() {
    __shared__ int ws[32];
    int tid = threadIdx.x, lane = tid & 31, w = tid >> 5;
    int i = blockIdx.x*1024 + tid;
    int v = (i < NN) ? g_deg[i] : 0;
    if (i < NN) g_dinv[i] = rsqrtf((float)(v + 1));  // +1 self loop
    int x = v;
    #pragma unroll
    for (int d = 1; d < 32; d <<= 1) {
        int y = __shfl_up_sync(0xFFFFFFFFu, x, d);
        if (lane >= d) x += y;
    }
    if (lane == 31) ws[w] = x;
    __syncthreads();
    if (w == 0) {
        int y = ws[lane];
        #pragma unroll
        for (int d = 1; d < 32; d <<= 1) {
            int z = __shfl_up_sync(0xFFFFFFFFu, y, d);
            if (lane >= d) y += z;
        }
        ws[lane] = y;
    }
    __syncthreads();
    int excl = x - v + (w > 0 ? ws[w-1] : 0);
    if (i < NN) g_off[i] = excl;
    if (tid == 1023) g_bsum[blockIdx.x] = ws[31];
}
__global__ void k_scanB() {
    __shared__ int wtot[2];
    int tid = threadIdx.x, lane = tid & 31, w = tid >> 5;
    int v = (tid < NCHUNK) ? g_bsum[tid] : 0;
    int x = v;
    #pragma unroll
    for (int d = 1; d < 32; d <<= 1) {
        int y = __shfl_up_sync(0xFFFFFFFFu, x, d);
        if (lane >= d) x += y;
    }
    if (lane == 31) wtot[w] = x;
    __syncthreads();
    if (w == 1) x += wtot[0];
    if (tid < NCHUNK) g_bsum[tid] = x - v;
    if (tid == 0) g_off[NN] = wtot[0] + wtot[1];
}
__global__ void k_scanC() {
    int i = blockIdx.x*blockDim.x + threadIdx.x;
    if (i < NN) {
        int o = g_off[i] + g_bsum[i >> 10];
        g_off[i] = o;
        g_cur[i] = o;
    }
}
__global__ void k_fill(const int* __restrict__ row, const int* __restrict__ col) {
    int i = blockIdx.x*blockDim.x + threadIdx.x;
    if (i < NE) {
        int pos = atomicAdd(&g_cur[col[i]], 1);
        g_src[pos] = row[i];
    }
}

// ---------------- precompute: folded weights + bf16 weights ----------------
// blocks 0..15  : M = We2@Wc1c tile (8 rows each), smem-staged We2, coalesced Wc1c
// block  16     : c1p = bc1 + be2@Wc1c
// blocks 17..312: bf16 conversions for idx in [16384, 92160)
__global__ void k_prep(const float* __restrict__ We2, const float* __restrict__ Wc1,
                       const float* __restrict__ be2, const float* __restrict__ bc1,
                       const float* __restrict__ Wc2, const float* __restrict__ W2,
                       const float* __restrict__ W3, const float* __restrict__ We1,
                       const float* __restrict__ be1) {
    const float* Wc1c = Wc1 + 256*HD;
    int tid = threadIdx.x;
    if (blockIdx.x < 16) {
        __shared__ float sW[8*HD];
        int r0 = blockIdx.x * 8;
        for (int i = tid; i < 8*HD; i += 256) sW[i] = __ldg(We2 + r0*HD + i);
        __syncthreads();
        int rr = tid >> 7;        // 0..1
        int n  = tid & 127;
        for (int r = rr; r < 8; r += 2) {
            float s = 0.f;
            #pragma unroll 8
            for (int k = 0; k < HD; k++) s += sW[r*HD + k] * __ldg(Wc1c + k*HD + n);
            g_B1[(r0 + r)*HD + n] = __float2bfloat16(s);
        }
    } else if (blockIdx.x == 16) {
        if (tid < 128) {
            float c = __ldg(bc1 + tid);
            #pragma unroll 8
            for (int j = 0; j < HD; j++) c += __ldg(be2 + j) * __ldg(Wc1c + j*HD + tid);
            g_c1p[tid] = c;
        }
    } else {
        int idx = (blockIdx.x - 17)*256 + tid + 16384;   // 16384..92159
        if (idx < 24576) {
            int t = idx - 16384;
            g_B2[t] = __float2bfloat16(__ldg(Wc2 + t));
        } else if (idx < 40960) {
            int t = idx - 24576;
            g_Wb2[t] = __float2bfloat16(__ldg(W2 + t));
        } else if (idx < 57344) {
            int t = idx - 40960;
            g_Wb3[t] = __float2bfloat16(__ldg(W3 + t));
        } else if (idx < 73728) {
            int t = idx - 57344;
            g_WbU[t] = __float2bfloat16(__ldg(Wc1 + t));
        } else if (idx < 90112) {
            int t = idx - 73728;
            g_WbV[t] = __float2bfloat16(__ldg(Wc1 + HD*HD + t));
        } else if (idx < 92160) {
            int e = idx - 90112;      // 16x128 augmented [We1; be1; 0]
            int k = e >> 7, n = e & 127;
            float v = (k < 4) ? __ldg(We1 + k*HD + n) : (k == 4 ? __ldg(be1 + n) : 0.f);
            g_B0[e] = __float2bfloat16(v);
        }
    }
}

// ---------------- layer-1 transform (K=8): tb = bf16(dinv * (x@W1)) ----------------
__global__ void k_transform1(const float* __restrict__ x, const float* __restrict__ W1,
                             __nv_bfloat16* __restrict__ tout) {
    __shared__ float sx[64*FNI];
    __shared__ float sw[FNI*HD];
    int tid = threadIdx.x;  // 0..127
    for (int i = tid; i < FNI*HD; i += 128) sw[i] = W1[i];
    int r0 = blockIdx.x * 64;
    for (int i = tid; i < 64*FNI; i += 128) {
        int r = r0 + (i >> 3);
        sx[i] = (r < NN) ? x[r*FNI + (i & 7)] : 0.f;
    }
    __syncthreads();
    int c = (tid & 63) * 2;
    int half = tid >> 6;
    for (int m = half*32; m < half*32 + 32; m++) {
        int r = r0 + m;
        if (r >= NN) break;
        float a0 = 0.f, a1 = 0.f;
        #pragma unroll
        for (int k = 0; k < FNI; k++) {
            float xv = sx[m*FNI + k];
            a0 += xv * sw[k*HD + c];
            a1 += xv * sw[k*HD + c + 1];
        }
        float d = g_dinv[r];
        ((uint32_t*)tout)[(size_t)r*64 + (c >> 1)] = pack_bf16x2(d*a0, d*a1);
    }
}

// ---------------- node GEMM via mma.sync bf16 (bf16 A): outb = bf16((A@Wb) [*dinv]) ----------------
#define NSTR 136
#define O_NW 34816
#define SMEM_NODE_BYTES 69632

__global__ __launch_bounds__(256, 2) void k_node_mma(const __nv_bfloat16* __restrict__ A,
        const __nv_bfloat16* __restrict__ Wb,
        __nv_bfloat16* __restrict__ outb, int scaled) {
    extern __shared__ char smem[];
    uint32_t sbase = smem_u32(smem);
    uint32_t* sAu = (uint32_t*)smem;
    uint32_t* sWu = (uint32_t*)(smem + O_NW);
    int tid = threadIdx.x, wid = tid >> 5, lane = tid & 31;
    int r0 = blockIdx.x * 128;

    const uint32_t* wsrc = (const uint32_t*)Wb;
    const uint32_t* asrc = (const uint32_t*)A;
    for (int i = tid; i < 8192; i += 256) {
        int r = i >> 6, cp = i & 63;
        sWu[r*(NSTR/2) + cp] = __ldg(wsrc + i);
    }
    for (int i = tid; i < 8192; i += 256) {
        int m = i >> 6, kp = i & 63;
        int r = r0 + m; if (r >= NN) r = NN - 1;
        sAu[m*(NSTR/2) + kp] = __ldg(asrc + (size_t)r*64 + kp);
    }
    __syncthreads();

    int lr = lane & 15, lc = (lane >> 4) << 3;
    float acc[16][4];
    #pragma unroll
    for (int i = 0; i < 16; i++)
        #pragma unroll
        for (int j = 0; j < 4; j++) acc[i][j] = 0.f;
    #pragma unroll
    for (int k0 = 0; k0 < 8; k0++) {
        uint32_t a[4];
        ldsm_x4(a, sbase + ((16*wid + lr)*NSTR + k0*16 + lc)*2);
        #pragma unroll
        for (int nt2 = 0; nt2 < 8; nt2++) {
            uint32_t b[4];
            ldsm_x4_t(b, sbase + O_NW + ((k0*16 + lr)*NSTR + nt2*16 + lc)*2);
            mma_bf16(acc[2*nt2],     a, b[0], b[1]);
            mma_bf16(acc[2*nt2 + 1], a, b[2], b[3]);
        }
    }

    int rA = r0 + 16*wid + (lane >> 2);
    int rB = rA + 8;
    int q = lane & 3;
    if (rA < NN) {
        float s = scaled ? g_dinv[rA] : 1.f;
        uint32_t* ob = (uint32_t*)outb + (size_t)rA*64;
        #pragma unroll
        for (int nt = 0; nt < 16; nt++)
            ob[nt*4 + q] = pack_bf16x2(acc[nt][0]*s, acc[nt][1]*s);
    }
    if (rB < NN) {
        float s = scaled ? g_dinv[rB] : 1.f;
        uint32_t* ob = (uint32_t*)outb + (size_t)rB*64;
        #pragma unroll
        for (int nt = 0; nt < 16; nt++)
            ob[nt*4 + q] = pack_bf16x2(acc[nt][2]*s, acc[nt][3]*s);
    }
}

// ---------------- CSR gather-aggregate (bf16 in/out, unroll-4) ----------------
__global__ __launch_bounds__(256) void k_aggregate(const __nv_bfloat16* __restrict__ t,
        const float* __restrict__ b, __nv_bfloat16* __restrict__ outp) {
    int wid = threadIdx.x >> 5, lane = threadIdx.x & 31;
    int c = blockIdx.x * 8 + wid;
    int start = __ldg(&g_off[c]), end = __ldg(&g_off[c+1]);
    const uint2* T = (const uint2*)t;   // 32 uint2 per row (128 bf16)
    float ax = 0.f, ay = 0.f, az = 0.f, aw = 0.f;
    {   // self term
        uint2 sv = __ldg(T + (size_t)c*32 + lane);
        acc_bf16x2(sv.x, ax, ay);
        acc_bf16x2(sv.y, az, aw);
    }
    for (int base = start; base < end; base += 32) {
        int n = end - base;
        int myIdx = (lane < n) ? __ldg(&g_src[base + lane]) : 0;
        int cnt = min(32, n);
        int j = 0;
        for (; j + 4 <= cnt; j += 4) {
            int r0 = __shfl_sync(0xFFFFFFFFu, myIdx, j);
            int r1 = __shfl_sync(0xFFFFFFFFu, myIdx, j+1);
            int r2 = __shfl_sync(0xFFFFFFFFu, myIdx, j+2);
            int r3 = __shfl_sync(0xFFFFFFFFu, myIdx, j+3);
            uint2 v0 = __ldg(T + (size_t)r0*32 + lane);
            uint2 v1 = __ldg(T + (size_t)r1*32 + lane);
            uint2 v2 = __ldg(T + (size_t)r2*32 + lane);
            uint2 v3 = __ldg(T + (size_t)r3*32 + lane);
            acc_bf16x2(v0.x, ax, ay); acc_bf16x2(v0.y, az, aw);
            acc_bf16x2(v1.x, ax, ay); acc_bf16x2(v1.y, az, aw);
            acc_bf16x2(v2.x, ax, ay); acc_bf16x2(v2.y, az, aw);
            acc_bf16x2(v3.x, ax, ay); acc_bf16x2(v3.y, az, aw);
        }
        for (; j < cnt; j++) {
            int r = __shfl_sync(0xFFFFFFFFu, myIdx, j);
            uint2 v = __ldg(T + (size_t)r*32 + lane);
            acc_bf16x2(v.x, ax, ay);
            acc_bf16x2(v.y, az, aw);
        }
    }
    float d = g_dinv[c];
    float4 bb = __ldg((const float4*)b + lane);
    uint2 o;
    o.x = pack_bf16x2(fmaxf(d*ax + bb.x, 0.f), fmaxf(d*ay + bb.y, 0.f));
    o.y = pack_bf16x2(fmaxf(d*az + bb.z, 0.f), fmaxf(d*aw + bb.w, 0.f));
    ((uint2*)outp)[(size_t)c*32 + lane] = o;
}

// ---------------- fused edge MLP: sync-free, register-chained mma ----------------
#define SAS 136
#define SBS 72
#define O_SB1   0          // 128 x 68 words
#define O_SB2   34816      // 128 x 36 words
#define O_SW0   53248      // 16 x 68 words (B0 augmented)
#define O_SC1P  57600      // 128 f32
#define O_SWC3  58112      // 128 f32
#define O_SBC2  58624      // 64 f32
#define SMEM_EDGE_BYTES 58880

__global__ __launch_bounds__(256, 2) void k_edge_mlp(
        const int* __restrict__ row, const int* __restrict__ col,
        const float* __restrict__ ea,
        const float* __restrict__ bc2, const float* __restrict__ Wc3,
        const float* __restrict__ bc3,
        const uint32_t* __restrict__ U, const uint32_t* __restrict__ V,
        float* __restrict__ out) {
    extern __shared__ char smem[];
    uint32_t sbase = smem_u32(smem);
    int tid = threadIdx.x;
    int wid = tid >> 5, lane = tid & 31;

    float* sC1p = (float*)(smem + O_SC1P);
    float* sWc3 = (float*)(smem + O_SWC3);
    float* sbc2 = (float*)(smem + O_SBC2);
    uint32_t* sB1u = (uint32_t*)(smem + O_SB1);
    uint32_t* sB2u = (uint32_t*)(smem + O_SB2);
    uint32_t* sW0u = (uint32_t*)(smem + O_SW0);

    // ---- persistent loads (once per block) ----
    if (tid < 128) {
        sC1p[tid] = g_c1p[tid];
        sWc3[tid] = __ldg(Wc3 + tid);
        if (tid < 64) sbc2[tid] = __ldg(bc2 + tid);
    }
    {
        const uint32_t* src = (const uint32_t*)g_B1;
        for (int i = tid; i < 8192; i += 256) {
            int r = i >> 6, cp = i & 63;
            sB1u[r*(SAS/2) + cp] = __ldg(src + i);
        }
    }
    {
        const uint32_t* src = (const uint32_t*)g_B2;
        for (int i = tid; i < 4096; i += 256) {
            int r = i >> 5, cp = i & 31;
            sB2u[r*(SBS/2) + cp] = __ldg(src + i);
        }
    }
    {
        const uint32_t* src = (const uint32_t*)g_B0;
        for (int i = tid; i < 1024; i += 256) {
            int r = i >> 6, cp = i & 63;
            sW0u[r*(SAS/2) + cp] = __ldg(src + i);
        }
    }
    __syncthreads();   // the only block-wide sync

    int lr = lane & 15, lc = (lane >> 4) << 3;
    int g = lane >> 2, t = lane & 3;
    float c3a = __ldg(bc3 + 0), c3b = __ldg(bc3 + 1);

    for (int wt = blockIdx.x*8 + wid; wt < NWT; wt += EGRID*8) {
        int e0 = wt * 16;
        int eA = e0 + g, eB = eA + 8;
        int rI0 = __ldg(row + eA), cI0 = __ldg(col + eA);
        int rI1 = __ldg(row + eB), cI1 = __ldg(col + eB);

        // ea A-fragments with augmented K (k=4 is the ones column -> bias)
        uint32_t eaf[4];
        eaf[2] = 0; eaf[3] = 0;
        if (t < 2) {
            float2 vA = *(const float2*)(ea + (size_t)eA*4 + 2*t);
            float2 vB = *(const float2*)(ea + (size_t)eB*4 + 2*t);
            eaf[0] = pack_bf16x2(vA.x, vA.y);
            eaf[1] = pack_bf16x2(vB.x, vB.y);
        } else if (t == 2) {
            eaf[0] = 0x00003F80u;   // (1.0, 0.0) bf16x2
            eaf[1] = 0x00003F80u;
        } else {
            eaf[0] = 0; eaf[1] = 0;
        }

        float acc[16][4];
        #pragma unroll
        for (int i = 0; i < 16; i++)
            #pragma unroll
            for (int j = 0; j < 4; j++) acc[i][j] = 0.f;

        // mma0: acc = [ea,1] @ [We1;be1]  (K=16, single k-step)
        #pragma unroll
        for (int nt2 = 0; nt2 < 8; nt2++) {
            uint32_t b[4];
            ldsm_x4_t(b, sbase + O_SW0 + (lr*SAS + nt2*16 + lc)*2);
            mma_bf16(acc[2*nt2],     eaf, b[0], b[1]);
            mma_bf16(acc[2*nt2 + 1], eaf, b[2], b[3]);
        }

        // relu -> A-fragments for GEMM1 (D->A register conversion)
        uint32_t af[8][4];
        #pragma unroll
        for (int kt = 0; kt < 8; kt++) {
            af[kt][0] = pack_bf16x2(fmaxf(acc[2*kt][0],   0.f), fmaxf(acc[2*kt][1],   0.f));
            af[kt][1] = pack_bf16x2(fmaxf(acc[2*kt][2],   0.f), fmaxf(acc[2*kt][3],   0.f));
            af[kt][2] = pack_bf16x2(fmaxf(acc[2*kt+1][0], 0.f), fmaxf(acc[2*kt+1][1], 0.f));
            af[kt][3] = pack_bf16x2(fmaxf(acc[2*kt+1][2], 0.f), fmaxf(acc[2*kt+1][3], 0.f));
        }

        // GEMM1: acc = a @ M
        #pragma unroll
        for (int i = 0; i < 16; i++)
            #pragma unroll
            for (int j = 0; j < 4; j++) acc[i][j] = 0.f;
        #pragma unroll
        for (int k0 = 0; k0 < 8; k0++) {
            #pragma unroll
            for (int nt2 = 0; nt2 < 8; nt2++) {
                uint32_t b[4];
                ldsm_x4_t(b, sbase + O_SB1 + ((k0*16 + lr)*SAS + nt2*16 + lc)*2);
                mma_bf16(acc[2*nt2],     af[k0], b[0], b[1]);
                mma_bf16(acc[2*nt2 + 1], af[k0], b[2], b[3]);
            }
        }

        // epilogue1: z1 = relu(acc + U[row] + V[col] + c1p) -> A-frags (in regs)
        {
            const uint32_t* U0 = U + (size_t)rI0*64;
            const uint32_t* V0 = V + (size_t)cI0*64;
            const uint32_t* U1 = U + (size_t)rI1*64;
            const uint32_t* V1 = V + (size_t)cI1*64;
            #pragma unroll
            for (int kt = 0; kt < 8; kt++) {
                int cw0 = kt*8 + t;
                int cw1 = kt*8 + 4 + t;
                uint32_t uA0 = __ldg(U0 + cw0), vA0 = __ldg(V0 + cw0);
                uint32_t uB0 = __ldg(U1 + cw0), vB0 = __ldg(V1 + cw0);
                uint32_t uA1 = __ldg(U0 + cw1), vA1 = __ldg(V0 + cw1);
                uint32_t uB1 = __ldg(U1 + cw1), vB1 = __ldg(V1 + cw1);
                int c0 = cw0*2, c1 = cw1*2;
                float p00 = sC1p[c0], p01 = sC1p[c0+1];
                float p10 = sC1p[c1], p11 = sC1p[c1+1];
                af[kt][0] = pack_bf16x2(
                    fmaxf(acc[2*kt][0] + bf_lo(uA0) + bf_lo(vA0) + p00, 0.f),
                    fmaxf(acc[2*kt][1] + bf_hi(uA0) + bf_hi(vA0) + p01, 0.f));
                af[kt][1] = pack_bf16x2(
                    fmaxf(acc[2*kt][2] + bf_lo(uB0) + bf_lo(vB0) + p00, 0.f),
                    fmaxf(acc[2*kt][3] + bf_hi(uB0) + bf_hi(vB0) + p01, 0.f));
                af[kt][2] = pack_bf16x2(
                    fmaxf(acc[2*kt+1][0] + bf_lo(uA1) + bf_lo(vA1) + p10, 0.f),
                    fmaxf(acc[2*kt+1][1] + bf_hi(uA1) + bf_hi(vA1) + p11, 0.f));
                af[kt][3] = pack_bf16x2(
                    fmaxf(acc[2*kt+1][2] + bf_lo(uB1) + bf_lo(vB1) + p10, 0.f),
                    fmaxf(acc[2*kt+1][3] + bf_hi(uB1) + bf_hi(vB1) + p11, 0.f));
            }
        }

        // GEMM2: acc[0..7] = z1 @ Wc2
        #pragma unroll
        for (int i = 0; i < 8; i++)
            #pragma unroll
            for (int j = 0; j < 4; j++) acc[i][j] = 0.f;
        #pragma unroll
        for (int k0 = 0; k0 < 8; k0++) {
            #pragma unroll
            for (int nt2 = 0; nt2 < 4; nt2++) {
                uint32_t b[4];
                ldsm_x4_t(b, sbase + O_SB2 + ((k0*16 + lr)*SBS + nt2*16 + lc)*2);
                mma_bf16(acc[2*nt2],     af[k0], b[0], b[1]);
                mma_bf16(acc[2*nt2 + 1], af[k0], b[2], b[3]);
            }
        }

        // epilogue2: z2 = relu(acc + bc2); logits; log_softmax
        {
            float l0a = 0.f, l1a = 0.f, l0b = 0.f, l1b = 0.f;
            #pragma unroll
            for (int nt = 0; nt < 8; nt++) {
                int c = nt*8 + 2*t;
                float b0 = sbc2[c], b1 = sbc2[c+1];
                float w00 = sWc3[2*c],   w01 = sWc3[2*c+1];
                float w10 = sWc3[2*c+2], w11 = sWc3[2*c+3];
                float za = fmaxf(acc[nt][0] + b0, 0.f);
                float zb = fmaxf(acc[nt][1] + b1, 0.f);
                l0a += za*w00 + zb*w10;
                l1a += za*w01 + zb*w11;
                float zc = fmaxf(acc[nt][2] + b0, 0.f);
                float zd = fmaxf(acc[nt][3] + b1, 0.f);
                l0b += zc*w00 + zd*w10;
                l1b += zc*w01 + zd*w11;
            }
            #pragma unroll
            for (int off = 1; off <= 2; off <<= 1) {
                l0a += __shfl_xor_sync(0xFFFFFFFFu, l0a, off);
                l1a += __shfl_xor_sync(0xFFFFFFFFu, l1a, off);
                l0b += __shfl_xor_sync(0xFFFFFFFFu, l0b, off);
                l1b += __shfl_xor_sync(0xFFFFFFFFu, l1b, off);
            }
            if (t == 0) {
                float L0 = l0a + c3a, L1 = l1a + c3b;
                float mx = fmaxf(L0, L1);
                float lse = mx + logf(expf(L0 - mx) + expf(L1 - mx));
                size_t o = (size_t)eA * 2;
                out[o + 0] = L0 - lse;
                out[o + 1] = L1 - lse;
                L0 = l0b + c3a; L1 = l1b + c3b;
                mx = fmaxf(L0, L1);
                lse = mx + logf(expf(L0 - mx) + expf(L1 - mx));
                o = (size_t)eB * 2;
                out[o + 0] = L0 - lse;
                out[o + 1] = L1 - lse;
            }
        }
    }
}

// ---------------- launch ----------------
extern "C" void kernel_launch(void* const* d_in, const int* in_sizes, int n_in,
                              void* d_out, int out_size) {
    const float* x   = (const float*)d_in[0];
    const int*   ei  = (const int*)  d_in[1];
    const float* ea  = (const float*)d_in[2];
    const float* W1  = (const float*)d_in[3];
    const float* b1  = (const float*)d_in[4];
    const float* W2  = (const float*)d_in[5];
    const float* b2  = (const float*)d_in[6];
    const float* W3  = (const float*)d_in[7];
    const float* b3  = (const float*)d_in[8];
    const float* We1 = (const float*)d_in[9];
    const float* be1 = (const float*)d_in[10];
    const float* We2 = (const float*)d_in[11];
    const float* be2 = (const float*)d_in[12];
    const float* Wc1 = (const float*)d_in[13];
    const float* bc1 = (const float*)d_in[14];
    const float* Wc2 = (const float*)d_in[15];
    const float* bc2 = (const float*)d_in[16];
    const float* Wc3 = (const float*)d_in[17];
    const float* bc3 = (const float*)d_in[18];
    float* out = (float*)d_out;
    const int* row = ei;
    const int* col = ei + NE;

    __nv_bfloat16 *h1, *h2, *tb, *ub, *vb;
    cudaGetSymbolAddress((void**)&h1, g_h1);
    cudaGetSymbolAddress((void**)&h2, g_h2);
    cudaGetSymbolAddress((void**)&tb, g_tb);
    cudaGetSymbolAddress((void**)&ub, g_Ub);
    cudaGetSymbolAddress((void**)&vb, g_Vb);
    __nv_bfloat16 *wb2, *wb3, *wbu, *wbv;
    cudaGetSymbolAddress((void**)&wb2, g_Wb2);
    cudaGetSymbolAddress((void**)&wb3, g_Wb3);
    cudaGetSymbolAddress((void**)&wbu, g_WbU);
    cudaGetSymbolAddress((void**)&wbv, g_WbV);
    int* degp;
    cudaGetSymbolAddress((void**)&degp, g_deg);

    cudaFuncSetAttribute(k_node_mma, cudaFuncAttributeMaxDynamicSharedMemorySize, SMEM_NODE_BYTES);
    cudaFuncSetAttribute(k_edge_mlp, cudaFuncAttributeMaxDynamicSharedMemorySize, SMEM_EDGE_BYTES);

    // graph preprocessing
    cudaMemsetAsync(degp, 0, NN*sizeof(int));
    k_deg_count<<<(NE + 255)/256, 256>>>(col);
    k_scanA    <<<NCHUNK, 1024>>>();
    k_scanB    <<<1, 64>>>();
    k_scanC    <<<(NN + 255)/256, 256>>>();
    k_fill     <<<(NE + 255)/256, 256>>>(row, col);
    k_prep     <<<313, 256>>>(We2, Wc1, be2, bc1, Wc2, W2, W3, We1, be1);

    const int NB = (NN + 127)/128;
    // layer 1
    k_transform1<<<(NN + 63)/64, 128>>>(x, W1, tb);
    k_aggregate <<<NN/8, 256>>>(tb, b1, h1);
    // layer 2
    k_node_mma  <<<NB, 256, SMEM_NODE_BYTES>>>(h1, wb2, tb, 1);
    k_aggregate <<<NN/8, 256>>>(tb, b2, h2);
    // layer 3
    k_node_mma  <<<NB, 256, SMEM_NODE_BYTES>>>(h2, wb3, tb, 1);
    k_aggregate <<<NN/8, 256>>>(tb, b3, h1);

    // U = h@Wc1[0:128], V = h@Wc1[128:256]  (bf16)
    k_node_mma  <<<NB, 256, SMEM_NODE_BYTES>>>(h1, wbu, ub, 0);
    k_node_mma  <<<NB, 256, SMEM_NODE_BYTES>>>(h1, wbv, vb, 0);

    k_edge_mlp<<<EGRID, 256, SMEM_EDGE_BYTES>>>(row, col, ea,
                                                bc2, Wc3, bc3,
                                                (const uint32_t*)ub, (const uint32_t*)vb, out);
}

// round 14
// speedup vs baseline: 1.0653x; 1.0531x over previous
#include <cuda_runtime.h>
#include <cuda_bf16.h>
#include <math.h>
#include <stdint.h>

#define NN 50000
#define NE 800000
#define HD 128
#define FNI 8
#define FEI 4
#define EGRID 148       // edge blocks: 1 per SM (occupancy 1, 8 warps)
#define NWT (NE/32)     // 25000 warp-tiles of 32 edges
#define NCHUNK 49       // ceil(NN/1024)

// ---------------- device scratch (no allocations allowed) ----------------
__device__ int   g_deg[NN];
__device__ int   g_off[NN+1];
__device__ int   g_cur[NN];
__device__ int   g_src[NE];
__device__ int   g_bsum[NCHUNK];
__device__ float g_dinv[NN];
__device__ __nv_bfloat16 g_h1[NN*HD];   // h accumulator A (bf16)
__device__ __nv_bfloat16 g_h2[NN*HD];   // h accumulator B (bf16)
__device__ __nv_bfloat16 g_tb[NN*HD];   // bf16 message buffer
__device__ __nv_bfloat16 g_Ub[NN*HD];   // bf16 U = h@Wc1[0:128]
__device__ __nv_bfloat16 g_Vb[NN*HD];   // bf16 V = h@Wc1[128:256]
__device__ float g_c1p[HD];    // bc1 + be2 @ Wc1[256:384]
__device__ __nv_bfloat16 g_B1[HD*HD];   // M = We2@Wc1c, row-major [k][n], bf16
__device__ __nv_bfloat16 g_B2[HD*64];   // Wc2 row-major [k][n], bf16
__device__ __nv_bfloat16 g_B0[16*HD];   // [We1; be1; 0] augmented-K, [k][n], bf16
__device__ __nv_bfloat16 g_Wb2[HD*HD];  // bf16 W2
__device__ __nv_bfloat16 g_Wb3[HD*HD];  // bf16 W3
__device__ __nv_bfloat16 g_WbU[HD*HD];  // bf16 Wc1[0:128]
__device__ __nv_bfloat16 g_WbV[HD*HD];  // bf16 Wc1[128:256]

// ---------------- PTX helpers ----------------
__device__ __forceinline__ uint32_t smem_u32(const void* p) {
    uint32_t a;
    asm("{ .reg .u64 t; cvta.to.shared.u64 t, %1; cvt.u32.u64 %0, t; }" : "=r"(a) : "l"(p));
    return a;
}
__device__ __forceinline__ void ldsm_x4(uint32_t* r, uint32_t addr) {
    asm volatile("ldmatrix.sync.aligned.m8n8.x4.shared.b16 {%0,%1,%2,%3}, [%4];"
        : "=r"(r[0]), "=r"(r[1]), "=r"(r[2]), "=r"(r[3]) : "r"(addr));
}
__device__ __forceinline__ void ldsm_x4_t(uint32_t* r, uint32_t addr) {
    asm volatile("ldmatrix.sync.aligned.m8n8.x4.trans.shared.b16 {%0,%1,%2,%3}, [%4];"
        : "=r"(r[0]), "=r"(r[1]), "=r"(r[2]), "=r"(r[3]) : "r"(addr));
}
__device__ __forceinline__ void mma_bf16(float* d, const uint32_t* a, uint32_t b0, uint32_t b1) {
    asm volatile("mma.sync.aligned.m16n8k16.row.col.f32.bf16.bf16.f32 "
        "{%0,%1,%2,%3}, {%4,%5,%6,%7}, {%8,%9}, {%0,%1,%2,%3};"
        : "+f"(d[0]), "+f"(d[1]), "+f"(d[2]), "+f"(d[3])
        : "r"(a[0]), "r"(a[1]), "r"(a[2]), "r"(a[3]), "r"(b0), "r"(b1));
}
__device__ __forceinline__ uint32_t pack_bf16x2(float lo, float hi) {
    uint32_t p;
    asm("cvt.rn.bf16x2.f32 %0, %1, %2;" : "=r"(p) : "f"(hi), "f"(lo));
    return p;
}
__device__ __forceinline__ void acc_bf16x2(uint32_t u, float& lo, float& hi) {
    lo += __uint_as_float(u << 16);
    hi += __uint_as_float(u & 0xFFFF0000u);
}
__device__ __forceinline__ float bf_lo(uint32_t u) { return __uint_as_float(u << 16); }
__device__ __forceinline__ float bf_hi(uint32_t u) { return __uint_as_float(u & 0xFFFF0000u); }

// ---------------- degree / norm / CSR ----------------
__global__ void k_deg_count(const int* __restrict__ col) {
    int i = blockIdx.x*blockDim.x + threadIdx.x;
    if (i < NE) atomicAdd(&g_deg[col[i]], 1);
}
__global__ __launch_bounds__(1024) void k_scanA() {
    __shared__ int ws[32];
    int tid = threadIdx.x, lane = tid & 31, w = tid >> 5;
    int i = blockIdx.x*1024 + tid;
    int v = (i < NN) ? g_deg[i] : 0;
    if (i < NN) g_dinv[i] = rsqrtf((float)(v + 1));  // +1 self loop
    int x = v;
    #pragma unroll
    for (int d = 1; d < 32; d <<= 1) {
        int y = __shfl_up_sync(0xFFFFFFFFu, x, d);
        if (lane >= d) x += y;
    }
    if (lane == 31) ws[w] = x;
    __syncthreads();
    if (w == 0) {
        int y = ws[lane];
        #pragma unroll
        for (int d = 1; d < 32; d <<= 1) {
            int z = __shfl_up_sync(0xFFFFFFFFu, y, d);
            if (lane >= d) y += z;
        }
        ws[lane] = y;
    }
    __syncthreads();
    int excl = x - v + (w > 0 ? ws[w-1] : 0);
    if (i < NN) g_off[i] = excl;
    if (tid == 1023) g_bsum[blockIdx.x] = ws[31];
}
__global__ void k_scanB() {
    __shared__ int wtot[2];
    int tid = threadIdx.x, lane = tid & 31, w = tid >> 5;
    int v = (tid < NCHUNK) ? g_bsum[tid] : 0;
    int x = v;
    #pragma unroll
    for (int d = 1; d < 32; d <<= 1) {
        int y = __shfl_up_sync(0xFFFFFFFFu, x, d);
        if (lane >= d) x += y;
    }
    if (lane == 31) wtot[w] = x;
    __syncthreads();
    if (w == 1) x += wtot[0];
    if (tid < NCHUNK) g_bsum[tid] = x - v;
    if (tid == 0) g_off[NN] = wtot[0] + wtot[1];
}
__global__ void k_scanC() {
    int i = blockIdx.x*blockDim.x + threadIdx.x;
    if (i < NN) {
        int o = g_off[i] + g_bsum[i >> 10];
        g_off[i] = o;
        g_cur[i] = o;
    }
}
__global__ void k_fill(const int* __restrict__ row, const int* __restrict__ col) {
    int i = blockIdx.x*blockDim.x + threadIdx.x;
    if (i < NE) {
        int pos = atomicAdd(&g_cur[col[i]], 1);
        g_src[pos] = row[i];
    }
}

// ---------------- precompute: folded weights + bf16 weights ----------------
__global__ void k_prep(const float* __restrict__ We2, const float* __restrict__ Wc1,
                       const float* __restrict__ be2, const float* __restrict__ bc1,
                       const float* __restrict__ Wc2, const float* __restrict__ W2,
                       const float* __restrict__ W3, const float* __restrict__ We1,
                       const float* __restrict__ be1) {
    const float* Wc1c = Wc1 + 256*HD;
    int tid = threadIdx.x;
    if (blockIdx.x < 16) {
        __shared__ float sW[8*HD];
        int r0 = blockIdx.x * 8;
        for (int i = tid; i < 8*HD; i += 256) sW[i] = __ldg(We2 + r0*HD + i);
        __syncthreads();
        int rr = tid >> 7;        // 0..1
        int n  = tid & 127;
        for (int r = rr; r < 8; r += 2) {
            float s = 0.f;
            #pragma unroll 8
            for (int k = 0; k < HD; k++) s += sW[r*HD + k] * __ldg(Wc1c + k*HD + n);
            g_B1[(r0 + r)*HD + n] = __float2bfloat16(s);
        }
    } else if (blockIdx.x == 16) {
        if (tid < 128) {
            float c = __ldg(bc1 + tid);
            #pragma unroll 8
            for (int j = 0; j < HD; j++) c += __ldg(be2 + j) * __ldg(Wc1c + j*HD + tid);
            g_c1p[tid] = c;
        }
    } else {
        int idx = (blockIdx.x - 17)*256 + tid + 16384;   // 16384..92159
        if (idx < 24576) {
            int t = idx - 16384;
            g_B2[t] = __float2bfloat16(__ldg(Wc2 + t));
        } else if (idx < 40960) {
            int t = idx - 24576;
            g_Wb2[t] = __float2bfloat16(__ldg(W2 + t));
        } else if (idx < 57344) {
            int t = idx - 40960;
            g_Wb3[t] = __float2bfloat16(__ldg(W3 + t));
        } else if (idx < 73728) {
            int t = idx - 57344;
            g_WbU[t] = __float2bfloat16(__ldg(Wc1 + t));
        } else if (idx < 90112) {
            int t = idx - 73728;
            g_WbV[t] = __float2bfloat16(__ldg(Wc1 + HD*HD + t));
        } else if (idx < 92160) {
            int e = idx - 90112;      // 16x128 augmented [We1; be1; 0]
            int k = e >> 7, n = e & 127;
            float v = (k < 4) ? __ldg(We1 + k*HD + n) : (k == 4 ? __ldg(be1 + n) : 0.f);
            g_B0[e] = __float2bfloat16(v);
        }
    }
}

// ---------------- layer-1 transform (K=8): tb = bf16(dinv * (x@W1)) ----------------
__global__ void k_transform1(const float* __restrict__ x, const float* __restrict__ W1,
                             __nv_bfloat16* __restrict__ tout) {
    __shared__ float sx[64*FNI];
    __shared__ float sw[FNI*HD];
    int tid = threadIdx.x;  // 0..127
    for (int i = tid; i < FNI*HD; i += 128) sw[i] = W1[i];
    int r0 = blockIdx.x * 64;
    for (int i = tid; i < 64*FNI; i += 128) {
        int r = r0 + (i >> 3);
        sx[i] = (r < NN) ? x[r*FNI + (i & 7)] : 0.f;
    }
    __syncthreads();
    int c = (tid & 63) * 2;
    int half = tid >> 6;
    for (int m = half*32; m < half*32 + 32; m++) {
        int r = r0 + m;
        if (r >= NN) break;
        float a0 = 0.f, a1 = 0.f;
        #pragma unroll
        for (int k = 0; k < FNI; k++) {
            float xv = sx[m*FNI + k];
            a0 += xv * sw[k*HD + c];
            a1 += xv * sw[k*HD + c + 1];
        }
        float d = g_dinv[r];
        ((uint32_t*)tout)[(size_t)r*64 + (c >> 1)] = pack_bf16x2(d*a0, d*a1);
    }
}

// ---------------- node GEMM via mma.sync bf16 (bf16 A): outb = bf16((A@Wb) [*dinv]) ----------------
#define NSTR 136
#define O_NW 34816
#define SMEM_NODE_BYTES 69632

__global__ __launch_bounds__(256, 2) void k_node_mma(const __nv_bfloat16* __restrict__ A,
        const __nv_bfloat16* __restrict__ Wb,
        __nv_bfloat16* __restrict__ outb, int scaled) {
    extern __shared__ char smem[];
    uint32_t sbase = smem_u32(smem);
    uint32_t* sAu = (uint32_t*)smem;
    uint32_t* sWu = (uint32_t*)(smem + O_NW);
    int tid = threadIdx.x, wid = tid >> 5, lane = tid & 31;
    int r0 = blockIdx.x * 128;

    const uint32_t* wsrc = (const uint32_t*)Wb;
    const uint32_t* asrc = (const uint32_t*)A;
    for (int i = tid; i < 8192; i += 256) {
        int r = i >> 6, cp = i & 63;
        sWu[r*(NSTR/2) + cp] = __ldg(wsrc + i);
    }
    for (int i = tid; i < 8192; i += 256) {
        int m = i >> 6, kp = i & 63;
        int r = r0 + m; if (r >= NN) r = NN - 1;
        sAu[m*(NSTR/2) + kp] = __ldg(asrc + (size_t)r*64 + kp);
    }
    __syncthreads();

    int lr = lane & 15, lc = (lane >> 4) << 3;
    float acc[16][4];
    #pragma unroll
    for (int i = 0; i < 16; i++)
        #pragma unroll
        for (int j = 0; j < 4; j++) acc[i][j] = 0.f;
    #pragma unroll
    for (int k0 = 0; k0 < 8; k0++) {
        uint32_t a[4];
        ldsm_x4(a, sbase + ((16*wid + lr)*NSTR + k0*16 + lc)*2);
        #pragma unroll
        for (int nt2 = 0; nt2 < 8; nt2++) {
            uint32_t b[4];
            ldsm_x4_t(b, sbase + O_NW + ((k0*16 + lr)*NSTR + nt2*16 + lc)*2);
            mma_bf16(acc[2*nt2],     a, b[0], b[1]);
            mma_bf16(acc[2*nt2 + 1], a, b[2], b[3]);
        }
    }

    int rA = r0 + 16*wid + (lane >> 2);
    int rB = rA + 8;
    int q = lane & 3;
    if (rA < NN) {
        float s = scaled ? g_dinv[rA] : 1.f;
        uint32_t* ob = (uint32_t*)outb + (size_t)rA*64;
        #pragma unroll
        for (int nt = 0; nt < 16; nt++)
            ob[nt*4 + q] = pack_bf16x2(acc[nt][0]*s, acc[nt][1]*s);
    }
    if (rB < NN) {
        float s = scaled ? g_dinv[rB] : 1.f;
        uint32_t* ob = (uint32_t*)outb + (size_t)rB*64;
        #pragma unroll
        for (int nt = 0; nt < 16; nt++)
            ob[nt*4 + q] = pack_bf16x2(acc[nt][2]*s, acc[nt][3]*s);
    }
}

// ---------------- CSR gather-aggregate (bf16 in/out, unroll-4) ----------------
__global__ __launch_bounds__(256) void k_aggregate(const __nv_bfloat16* __restrict__ t,
        const float* __restrict__ b, __nv_bfloat16* __restrict__ outp) {
    int wid = threadIdx.x >> 5, lane = threadIdx.x & 31;
    int c = blockIdx.x * 8 + wid;
    int start = __ldg(&g_off[c]), end = __ldg(&g_off[c+1]);
    const uint2* T = (const uint2*)t;   // 32 uint2 per row (128 bf16)
    float ax = 0.f, ay = 0.f, az = 0.f, aw = 0.f;
    {   // self term
        uint2 sv = __ldg(T + (size_t)c*32 + lane);
        acc_bf16x2(sv.x, ax, ay);
        acc_bf16x2(sv.y, az, aw);
    }
    for (int base = start; base < end; base += 32) {
        int n = end - base;
        int myIdx = (lane < n) ? __ldg(&g_src[base + lane]) : 0;
        int cnt = min(32, n);
        int j = 0;
        for (; j + 4 <= cnt; j += 4) {
            int r0 = __shfl_sync(0xFFFFFFFFu, myIdx, j);
            int r1 = __shfl_sync(0xFFFFFFFFu, myIdx, j+1);
            int r2 = __shfl_sync(0xFFFFFFFFu, myIdx, j+2);
            int r3 = __shfl_sync(0xFFFFFFFFu, myIdx, j+3);
            uint2 v0 = __ldg(T + (size_t)r0*32 + lane);
            uint2 v1 = __ldg(T + (size_t)r1*32 + lane);
            uint2 v2 = __ldg(T + (size_t)r2*32 + lane);
            uint2 v3 = __ldg(T + (size_t)r3*32 + lane);
            acc_bf16x2(v0.x, ax, ay); acc_bf16x2(v0.y, az, aw);
            acc_bf16x2(v1.x, ax, ay); acc_bf16x2(v1.y, az, aw);
            acc_bf16x2(v2.x, ax, ay); acc_bf16x2(v2.y, az, aw);
            acc_bf16x2(v3.x, ax, ay); acc_bf16x2(v3.y, az, aw);
        }
        for (; j < cnt; j++) {
            int r = __shfl_sync(0xFFFFFFFFu, myIdx, j);
            uint2 v = __ldg(T + (size_t)r*32 + lane);
            acc_bf16x2(v.x, ax, ay);
            acc_bf16x2(v.y, az, aw);
        }
    }
    float d = g_dinv[c];
    float4 bb = __ldg((const float4*)b + lane);
    uint2 o;
    o.x = pack_bf16x2(fmaxf(d*ax + bb.x, 0.f), fmaxf(d*ay + bb.y, 0.f));
    o.y = pack_bf16x2(fmaxf(d*az + bb.z, 0.f), fmaxf(d*aw + bb.w, 0.f));
    ((uint2*)outp)[(size_t)c*32 + lane] = o;
}

// ---------------- fused edge MLP: M=32 per warp, register-chained mma ----------------
#define SAS 136
#define SBS 72
#define O_SB1   0          // 128 x 68 words
#define O_SB2   34816      // 128 x 36 words
#define O_SW0   53248      // 16 x 68 words (B0 augmented)
#define O_SC1P  57600      // 128 f32
#define O_SWC3  58112      // 128 f32
#define O_SBC2  58624      // 64 f32
#define SMEM_EDGE_BYTES 58880

__global__ __launch_bounds__(256, 1) void k_edge_mlp(
        const int* __restrict__ row, const int* __restrict__ col,
        const float* __restrict__ ea,
        const float* __restrict__ bc2, const float* __restrict__ Wc3,
        const float* __restrict__ bc3,
        const uint32_t* __restrict__ U, const uint32_t* __restrict__ V,
        float* __restrict__ out) {
    extern __shared__ char smem[];
    uint32_t sbase = smem_u32(smem);
    int tid = threadIdx.x;
    int wid = tid >> 5, lane = tid & 31;

    float* sC1p = (float*)(smem + O_SC1P);
    float* sWc3 = (float*)(smem + O_SWC3);
    float* sbc2 = (float*)(smem + O_SBC2);
    uint32_t* sB1u = (uint32_t*)(smem + O_SB1);
    uint32_t* sB2u = (uint32_t*)(smem + O_SB2);
    uint32_t* sW0u = (uint32_t*)(smem + O_SW0);

    // ---- persistent loads (once per block) ----
    if (tid < 128) {
        sC1p[tid] = g_c1p[tid];
        sWc3[tid] = __ldg(Wc3 + tid);
        if (tid < 64) sbc2[tid] = __ldg(bc2 + tid);
    }
    {
        const uint32_t* src = (const uint32_t*)g_B1;
        for (int i = tid; i < 8192; i += 256) {
            int r = i >> 6, cp = i & 63;
            sB1u[r*(SAS/2) + cp] = __ldg(src + i);
        }
    }
    {
        const uint32_t* src = (const uint32_t*)g_B2;
        for (int i = tid; i < 4096; i += 256) {
            int r = i >> 5, cp = i & 31;
            sB2u[r*(SBS/2) + cp] = __ldg(src + i);
        }
    }
    {
        const uint32_t* src = (const uint32_t*)g_B0;
        for (int i = tid; i < 1024; i += 256) {
            int r = i >> 6, cp = i & 63;
            sW0u[r*(SAS/2) + cp] = __ldg(src + i);
        }
    }
    __syncthreads();   // the only block-wide sync

    int lr = lane & 15, lc = (lane >> 4) << 3;
    int g = lane >> 2, t = lane & 3;
    float c3a = __ldg(bc3 + 0), c3b = __ldg(bc3 + 1);

    for (int wt = blockIdx.x*8 + wid; wt < NWT; wt += EGRID*8) {
        int e0 = wt * 32;

        // ---- ea A-fragments for both 16-row blocks (augmented K) ----
        uint32_t eaf[2][4];
        #pragma unroll
        for (int b = 0; b < 2; b++) {
            int eA = e0 + b*16 + g, eB = eA + 8;
            eaf[b][2] = 0; eaf[b][3] = 0;
            if (t < 2) {
                float2 vA = *(const float2*)(ea + (size_t)eA*4 + 2*t);
                float2 vB = *(const float2*)(ea + (size_t)eB*4 + 2*t);
                eaf[b][0] = pack_bf16x2(vA.x, vA.y);
                eaf[b][1] = pack_bf16x2(vB.x, vB.y);
            } else if (t == 2) {
                eaf[b][0] = 0x00003F80u;
                eaf[b][1] = 0x00003F80u;
            } else {
                eaf[b][0] = 0; eaf[b][1] = 0;
            }
        }

        float acc[2][16][4];
        #pragma unroll
        for (int b = 0; b < 2; b++)
            #pragma unroll
            for (int i = 0; i < 16; i++)
                #pragma unroll
                for (int j = 0; j < 4; j++) acc[b][i][j] = 0.f;

        // mma0: acc = [ea,1] @ [We1;be1]  (B loaded once, used for both blocks)
        #pragma unroll
        for (int nt2 = 0; nt2 < 8; nt2++) {
            uint32_t b[4];
            ldsm_x4_t(b, sbase + O_SW0 + (lr*SAS + nt2*16 + lc)*2);
            mma_bf16(acc[0][2*nt2],     eaf[0], b[0], b[1]);
            mma_bf16(acc[0][2*nt2 + 1], eaf[0], b[2], b[3]);
            mma_bf16(acc[1][2*nt2],     eaf[1], b[0], b[1]);
            mma_bf16(acc[1][2*nt2 + 1], eaf[1], b[2], b[3]);
        }

        // relu -> A-fragments
        uint32_t af[2][8][4];
        #pragma unroll
        for (int b = 0; b < 2; b++)
            #pragma unroll
            for (int kt = 0; kt < 8; kt++) {
                af[b][kt][0] = pack_bf16x2(fmaxf(acc[b][2*kt][0],   0.f), fmaxf(acc[b][2*kt][1],   0.f));
                af[b][kt][1] = pack_bf16x2(fmaxf(acc[b][2*kt][2],   0.f), fmaxf(acc[b][2*kt][3],   0.f));
                af[b][kt][2] = pack_bf16x2(fmaxf(acc[b][2*kt+1][0], 0.f), fmaxf(acc[b][2*kt+1][1], 0.f));
                af[b][kt][3] = pack_bf16x2(fmaxf(acc[b][2*kt+1][2], 0.f), fmaxf(acc[b][2*kt+1][3], 0.f));
            }

        // GEMM1: acc = a @ M
        #pragma unroll
        for (int b = 0; b < 2; b++)
            #pragma unroll
            for (int i = 0; i < 16; i++)
                #pragma unroll
                for (int j = 0; j < 4; j++) acc[b][i][j] = 0.f;
        #pragma unroll
        for (int k0 = 0; k0 < 8; k0++) {
            #pragma unroll
            for (int nt2 = 0; nt2 < 8; nt2++) {
                uint32_t b[4];
                ldsm_x4_t(b, sbase + O_SB1 + ((k0*16 + lr)*SAS + nt2*16 + lc)*2);
                mma_bf16(acc[0][2*nt2],     af[0][k0], b[0], b[1]);
                mma_bf16(acc[0][2*nt2 + 1], af[0][k0], b[2], b[3]);
                mma_bf16(acc[1][2*nt2],     af[1][k0], b[0], b[1]);
                mma_bf16(acc[1][2*nt2 + 1], af[1][k0], b[2], b[3]);
            }
        }

        // epilogue1: z1 = relu(acc + U[row] + V[col] + c1p) -> A-frags
        #pragma unroll
        for (int b = 0; b < 2; b++) {
            int eA = e0 + b*16 + g, eB = eA + 8;
            int rI0 = __ldg(row + eA), cI0 = __ldg(col + eA);
            int rI1 = __ldg(row + eB), cI1 = __ldg(col + eB);
            const uint32_t* U0 = U + (size_t)rI0*64;
            const uint32_t* V0 = V + (size_t)cI0*64;
            const uint32_t* U1 = U + (size_t)rI1*64;
            const uint32_t* V1 = V + (size_t)cI1*64;
            #pragma unroll
            for (int kt = 0; kt < 8; kt++) {
                int cw0 = kt*8 + t;
                int cw1 = kt*8 + 4 + t;
                uint32_t uA0 = __ldg(U0 + cw0), vA0 = __ldg(V0 + cw0);
                uint32_t uB0 = __ldg(U1 + cw0), vB0 = __ldg(V1 + cw0);
                uint32_t uA1 = __ldg(U0 + cw1), vA1 = __ldg(V0 + cw1);
                uint32_t uB1 = __ldg(U1 + cw1), vB1 = __ldg(V1 + cw1);
                int c0 = cw0*2, c1 = cw1*2;
                float p00 = sC1p[c0], p01 = sC1p[c0+1];
                float p10 = sC1p[c1], p11 = sC1p[c1+1];
                af[b][kt][0] = pack_bf16x2(
                    fmaxf(acc[b][2*kt][0] + bf_lo(uA0) + bf_lo(vA0) + p00, 0.f),
                    fmaxf(acc[b][2*kt][1] + bf_hi(uA0) + bf_hi(vA0) + p01, 0.f));
                af[b][kt][1] = pack_bf16x2(
                    fmaxf(acc[b][2*kt][2] + bf_lo(uB0) + bf_lo(vB0) + p00, 0.f),
                    fmaxf(acc[b][2*kt][3] + bf_hi(uB0) + bf_hi(vB0) + p01, 0.f));
                af[b][kt][2] = pack_bf16x2(
                    fmaxf(acc[b][2*kt+1][0] + bf_lo(uA1) + bf_lo(vA1) + p10, 0.f),
                    fmaxf(acc[b][2*kt+1][1] + bf_hi(uA1) + bf_hi(vA1) + p11, 0.f));
                af[b][kt][3] = pack_bf16x2(
                    fmaxf(acc[b][2*kt+1][2] + bf_lo(uB1) + bf_lo(vB1) + p10, 0.f),
                    fmaxf(acc[b][2*kt+1][3] + bf_hi(uB1) + bf_hi(vB1) + p11, 0.f));
            }
        }

        // GEMM2: acc[.][0..7] = z1 @ Wc2
        #pragma unroll
        for (int b = 0; b < 2; b++)
            #pragma unroll
            for (int i = 0; i < 8; i++)
                #pragma unroll
                for (int j = 0; j < 4; j++) acc[b][i][j] = 0.f;
        #pragma unroll
        for (int k0 = 0; k0 < 8; k0++) {
            #pragma unroll
            for (int nt2 = 0; nt2 < 4; nt2++) {
                uint32_t b[4];
                ldsm_x4_t(b, sbase + O_SB2 + ((k0*16 + lr)*SBS + nt2*16 + lc)*2);
                mma_bf16(acc[0][2*nt2],     af[0][k0], b[0], b[1]);
                mma_bf16(acc[0][2*nt2 + 1], af[0][k0], b[2], b[3]);
                mma_bf16(acc[1][2*nt2],     af[1][k0], b[0], b[1]);
                mma_bf16(acc[1][2*nt2 + 1], af[1][k0], b[2], b[3]);
            }
        }

        // epilogue2: z2 = relu(acc + bc2); logits; log_softmax
        #pragma unroll
        for (int b = 0; b < 2; b++) {
            int eA = e0 + b*16 + g, eB = eA + 8;
            float l0a = 0.f, l1a = 0.f, l0b = 0.f, l1b = 0.f;
            #pragma unroll
            for (int nt = 0; nt < 8; nt++) {
                int c = nt*8 + 2*t;
                float b0 = sbc2[c], b1 = sbc2[c+1];
                float w00 = sWc3[2*c],   w01 = sWc3[2*c+1];
                float w10 = sWc3[2*c+2], w11 = sWc3[2*c+3];
                float za = fmaxf(acc[b][nt][0] + b0, 0.f);
                float zb = fmaxf(acc[b][nt][1] + b1, 0.f);
                l0a += za*w00 + zb*w10;
                l1a += za*w01 + zb*w11;
                float zc = fmaxf(acc[b][nt][2] + b0, 0.f);
                float zd = fmaxf(acc[b][nt][3] + b1, 0.f);
                l0b += zc*w00 + zd*w10;
                l1b += zc*w01 + zd*w11;
            }
            #pragma unroll
            for (int off = 1; off <= 2; off <<= 1) {
                l0a += __shfl_xor_sync(0xFFFFFFFFu, l0a, off);
                l1a += __shfl_xor_sync(0xFFFFFFFFu, l1a, off);
                l0b += __shfl_xor_sync(0xFFFFFFFFu, l0b, off);
                l1b += __shfl_xor_sync(0xFFFFFFFFu, l1b, off);
            }
            if (t == 0) {
                float L0 = l0a + c3a, L1 = l1a + c3b;
                float mx = fmaxf(L0, L1);
                float lse = mx + logf(expf(L0 - mx) + expf(L1 - mx));
                size_t o = (size_t)eA * 2;
                out[o + 0] = L0 - lse;
                out[o + 1] = L1 - lse;
                L0 = l0b + c3a; L1 = l1b + c3b;
                mx = fmaxf(L0, L1);
                lse = mx + logf(expf(L0 - mx) + expf(L1 - mx));
                o = (size_t)eB * 2;
                out[o + 0] = L0 - lse;
                out[o + 1] = L1 - lse;
            }
        }
    }
}

// ---------------- launch ----------------
extern "C" void kernel_launch(void* const* d_in, const int* in_sizes, int n_in,
                              void* d_out, int out_size) {
    const float* x   = (const float*)d_in[0];
    const int*   ei  = (const int*)  d_in[1];
    const float* ea  = (const float*)d_in[2];
    const float* W1  = (const float*)d_in[3];
    const float* b1  = (const float*)d_in[4];
    const float* W2  = (const float*)d_in[5];
    const float* b2  = (const float*)d_in[6];
    const float* W3  = (const float*)d_in[7];
    const float* b3  = (const float*)d_in[8];
    const float* We1 = (const float*)d_in[9];
    const float* be1 = (const float*)d_in[10];
    const float* We2 = (const float*)d_in[11];
    const float* be2 = (const float*)d_in[12];
    const float* Wc1 = (const float*)d_in[13];
    const float* bc1 = (const float*)d_in[14];
    const float* Wc2 = (const float*)d_in[15];
    const float* bc2 = (const float*)d_in[16];
    const float* Wc3 = (const float*)d_in[17];
    const float* bc3 = (const float*)d_in[18];
    float* out = (float*)d_out;
    const int* row = ei;
    const int* col = ei + NE;

    __nv_bfloat16 *h1, *h2, *tb, *ub, *vb;
    cudaGetSymbolAddress((void**)&h1, g_h1);
    cudaGetSymbolAddress((void**)&h2, g_h2);
    cudaGetSymbolAddress((void**)&tb, g_tb);
    cudaGetSymbolAddress((void**)&ub, g_Ub);
    cudaGetSymbolAddress((void**)&vb, g_Vb);
    __nv_bfloat16 *wb2, *wb3, *wbu, *wbv;
    cudaGetSymbolAddress((void**)&wb2, g_Wb2);
    cudaGetSymbolAddress((void**)&wb3, g_Wb3);
    cudaGetSymbolAddress((void**)&wbu, g_WbU);
    cudaGetSymbolAddress((void**)&wbv, g_WbV);
    int* degp;
    cudaGetSymbolAddress((void**)&degp, g_deg);

    cudaFuncSetAttribute(k_node_mma, cudaFuncAttributeMaxDynamicSharedMemorySize, SMEM_NODE_BYTES);
    cudaFuncSetAttribute(k_edge_mlp, cudaFuncAttributeMaxDynamicSharedMemorySize, SMEM_EDGE_BYTES);

    // graph preprocessing
    cudaMemsetAsync(degp, 0, NN*sizeof(int));
    k_deg_count<<<(NE + 255)/256, 256>>>(col);
    k_scanA    <<<NCHUNK, 1024>>>();
    k_scanB    <<<1, 64>>>();
    k_scanC    <<<(NN + 255)/256, 256>>>();
    k_fill     <<<(NE + 255)/256, 256>>>(row, col);
    k_prep     <<<313, 256>>>(We2, Wc1, be2, bc1, Wc2, W2, W3, We1, be1);

    const int NB = (NN + 127)/128;
    // layer 1
    k_transform1<<<(NN + 63)/64, 128>>>(x, W1, tb);
    k_aggregate <<<NN/8, 256>>>(tb, b1, h1);
    // layer 2
    k_node_mma  <<<NB, 256, SMEM_NODE_BYTES>>>(h1, wb2, tb, 1);
    k_aggregate <<<NN/8, 256>>>(tb, b2, h2);
    // layer 3
    k_node_mma  <<<NB, 256, SMEM_NODE_BYTES>>>(h2, wb3, tb, 1);
    k_aggregate <<<NN/8, 256>>>(tb, b3, h1);

    // U = h@Wc1[0:128], V = h@Wc1[128:256]  (bf16)
    k_node_mma  <<<NB, 256, SMEM_NODE_BYTES>>>(h1, wbu, ub, 0);
    k_node_mma  <<<NB, 256, SMEM_NODE_BYTES>>>(h1, wbv, vb, 0);

    k_edge_mlp<<<EGRID, 256, SMEM_EDGE_BYTES>>>(row, col, ea,
                                                bc2, Wc3, bc3,
                                                (const uint32_t*)ub, (const uint32_t*)vb, out);
}